// round 14
// baseline (speedup 1.0000x reference)
#include <cuda_runtime.h>
#include <math.h>

// B=2, D=H=W=128, C=4 image; label int32 C=1; coarse flow [2,4,4,4,3].
// Output: image [2,128,128,128,4] f32 then label [2,128,128,128] (as float).
// Intermediate flow PLANAR: [c][b][d][h][w]

#define NVOX      (2*128*128*128)
#define IMG_ELEMS (NVOX*4)
#define FLOW_N    (NVOX*3)

__device__ float d_F2[FLOW_N];  // after resize + convD, planar
__device__ float d_F3[FLOW_N];  // after convH + convW,   planar

// ---- packed f32x2 helpers (sm_103a) ----
#define PK2(out, lo, hi) \
    asm("mov.b64 %0, {%1, %2};" : "=l"(out) : "r"(__float_as_uint(lo)), "r"(__float_as_uint(hi)))
#define FMA2(d, a, b, c) \
    asm("fma.rn.f32x2 %0, %1, %2, %3;" : "=l"(d) : "l"(a), "l"(b), "l"(c))
#define UPK2(lo, hi, v) do { unsigned int _ulo, _uhi; \
    asm("mov.b64 {%0, %1}, %2;" : "=r"(_ulo), "=r"(_uhi) : "l"(v)); \
    lo = __uint_as_float(_ulo); hi = __uint_as_float(_uhi); } while (0)

// ---- weight generation (exact op structure jax/numpy use) ----
__device__ __forceinline__ float keys_f32(float x) {
    if (x < 1.0f) {
        float t = __fadd_rn(__fmul_rn(1.5f, x), -2.5f);
        t = __fmul_rn(t, x); t = __fmul_rn(t, x);
        return __fadd_rn(t, 1.0f);
    }
    if (x < 2.0f) {
        float t = __fadd_rn(__fmul_rn(-0.5f, x), 2.5f);
        t = __fadd_rn(__fmul_rn(t, x), -4.0f);
        t = __fmul_rn(t, x);
        return __fadd_rn(t, 2.0f);
    }
    return 0.0f;
}

__device__ __forceinline__ void gen_W_row(float* Wrow, int x) {
    float s = __fadd_rn(__fdiv_rn(__fadd_rn((float)x, 0.5f), 32.0f), -0.5f);
    float wv[4];
#pragma unroll
    for (int a = 0; a < 4; a++) wv[a] = keys_f32(fabsf(__fadd_rn(s, -(float)a)));
    float tot = __fadd_rn(__fadd_rn(__fadd_rn(wv[0], wv[1]), wv[2]), wv[3]);
#pragma unroll
    for (int a = 0; a < 4; a++) Wrow[a] = __fdiv_rn(wv[a], tot);
}

// ---------------- fused resizeD+resizeH+resizeW+convD (planar out, f32x2 conv) -------
__global__ __launch_bounds__(384) void flowD_kernel(const float* __restrict__ coarse) {
    __shared__ float  cf[192];
    __shared__ float4 A2h4[48 * 3];     // [ld][c] -> (e0,e1,e2,e3)
    __shared__ float  Ws[128][4];
    __shared__ float  Gs[16];
    __shared__ unsigned long long GG2[16];   // {g[j], g[j]}
    __shared__ double gtmp[16];
    const int t = threadIdx.x;
    const int t0 = blockIdx.x * 32;
    const int h = blockIdx.y, b = blockIdx.z;
    const int dplo = t0 - 7;

    if (t < 128) gen_W_row(Ws[t], t);
    if (t >= 128 && t < 144) { double o = (double)(t - 128 - 7); gtmp[t - 128] = exp(-o * o / 12.5); }
    if (t >= 192 && t < 384) cf[t - 192] = coarse[b * 192 + (t - 192)];
    __syncthreads();
    if (t < 16) {
        double gs = 0.0;
        for (int j = 0; j < 16; j++) gs += gtmp[j];
        const float gj = (float)(gtmp[t] / gs);
        Gs[t] = gj;
        unsigned long long p; PK2(p, gj, gj);
        GG2[t] = p;
    }
    __syncthreads();

    float* A2h = reinterpret_cast<float*>(A2h4);
    const float wh0 = Ws[h][0], wh1 = Ws[h][1], wh2 = Ws[h][2], wh3 = Ws[h][3];
    for (int i = t; i < 48 * 12; i += 384) {
        const int ld = i / 12, r = i - ld * 12;
        const int c = r >> 2, e = r & 3;          // transposed slot
        const int dp = dplo + ld;
        float acc = 0.0f;
        if (dp >= 0 && dp < 128) {
#pragma unroll
            for (int bb = 0; bb < 4; bb++) {
                float a1 = 0.0f;
#pragma unroll
                for (int a = 0; a < 4; a++)
                    a1 = fmaf(Ws[dp][a], cf[a * 48 + bb * 12 + e * 3 + c], a1);
                const float whb = (bb == 0) ? wh0 : (bb == 1) ? wh1 : (bb == 2) ? wh2 : wh3;
                acc = fmaf(whb, a1, acc);
            }
        }
        A2h[i] = acc;
    }
    __syncthreads();

    const int c = t >> 7, w = t & 127;
    const float ww0 = Ws[w][0], ww1 = Ws[w][1], ww2 = Ws[w][2], ww3 = Ws[w][3];

    auto b1 = [&](int ld) -> float {
        const int dp = dplo + ld;
        if (dp < 0 || dp >= 128) return 0.0f;
        const float4 v = A2h4[ld * 3 + c];        // broadcast LDS.128
        float acc = 0.0f;
        acc = fmaf(ww0, v.x, acc);
        acc = fmaf(ww1, v.y, acc);
        acc = fmaf(ww2, v.z, acc);
        acc = fmaf(ww3, v.w, acc);
        return acc;
    };

    // packed window ring: PW[k] = {win[k], win[k+1]}
    float prev = b1(0);
    unsigned long long PW[16];
#pragma unroll
    for (int j = 1; j <= 16; j++) { const float s = b1(j); PK2(PW[j - 1], prev, s); prev = s; }

    size_t obase = ((size_t)(c * 2 + b) << 21) + ((size_t)t0 << 14) + (h << 7) + w;
#pragma unroll
    for (int p = 0; p < 16; p++) {
        unsigned long long acc2 = 0ull;            // {+0.0f, +0.0f}
#pragma unroll
        for (int j = 0; j < 16; j++)
            FMA2(acc2, GG2[j], PW[(2 * p + j) & 15], acc2);   // j ascending: bit-exact per lane
        float lo, hi; UPK2(lo, hi, acc2);
        d_F2[obase] = lo;
        d_F2[obase + 16384] = hi;
        obase += 32768;
        if (p < 15) {
            const float s1 = b1(2 * p + 17); PK2(PW[(2 * p + 16) & 15], prev, s1); prev = s1;
            const float s2 = b1(2 * p + 18); PK2(PW[(2 * p + 17) & 15], prev, s2); prev = s2;
        }
    }
}

// ---------------- fused convH + convW (f32x2 convs; convH reads GLOBAL) --------------
// grid (8, 128, 2) = (h-tile of 16, d, b); 384 threads
// dyn smem: H [48][129]; OUT [48][129].  total 49536 B
extern __shared__ float dyn_smem[];
__global__ __launch_bounds__(384) void flowHW_kernel() {
    float* H   = dyn_smem;
    float* OUT = dyn_smem + 6192;
    __shared__ float  Gs[16];
    __shared__ unsigned long long GG2[16];
    __shared__ double gtmp[16];
    const int t = threadIdx.x;
    const int h0 = blockIdx.x * 16;
    const int d = blockIdx.y, b = blockIdx.z;

    if (t < 16) { double o = (double)(t - 7); gtmp[t] = exp(-o * o / 12.5); }
    __syncthreads();
    if (t < 16) {
        double gs = 0.0;
        for (int j = 0; j < 16; j++) gs += gtmp[j];
        const float gj = (float)(gtmp[t] / gs);
        Gs[t] = gj;
        unsigned long long p; PK2(p, gj, gj);
        GG2[t] = p;
    }
    __syncthreads();

    // convH: packed-pair sliding window, scalars straight from global F2
    {
        const int c = t >> 7, w = t & 127;
        const float* gcol = d_F2 + ((size_t)(c * 2 + b) << 21) + ((size_t)d << 14) + w;
        auto gv = [&](int j) -> float {
            const int hp = h0 - 7 + j;
            return (hp >= 0 && hp < 128) ? gcol[(size_t)hp << 7] : 0.0f;
        };
        float prev = gv(0);
        unsigned long long PW[16];
#pragma unroll
        for (int j = 1; j <= 16; j++) { const float s = gv(j); PK2(PW[j - 1], prev, s); prev = s; }

#pragma unroll
        for (int p = 0; p < 8; p++) {
            unsigned long long acc2 = 0ull;
#pragma unroll
            for (int j = 0; j < 16; j++)
                FMA2(acc2, GG2[j], PW[(2 * p + j) & 15], acc2);
            float lo, hi; UPK2(lo, hi, acc2);
            H[(c * 16 + 2 * p    ) * 129 + w] = lo;
            H[(c * 16 + 2 * p + 1) * 129 + w] = hi;
            if (p < 7) {
                const float s1 = gv(2 * p + 17); PK2(PW[(2 * p + 16) & 15], prev, s1); prev = s1;
                const float s2 = gv(2 * p + 18); PK2(PW[(2 * p + 17) & 15], prev, s2); prev = s2;
            }
        }
    }
    __syncthreads();

    // convW: packed-pair sliding window over smem row. chunk-major: t = q*48 + pi
    {
        const int q = t / 48, pi = t - q * 48;
        const int s0 = q * 16 - 7;
        const float* row = H + pi * 129;
        auto hv = [&](int s) -> float { return (s >= 0 && s < 128) ? row[s] : 0.0f; };
        float prev = hv(s0);
        unsigned long long PW[16];
#pragma unroll
        for (int j = 1; j <= 16; j++) { const float s = hv(s0 + j); PK2(PW[j - 1], prev, s); prev = s; }

        float* orow = OUT + pi * 129 + q * 16;
#pragma unroll
        for (int p = 0; p < 8; p++) {
            unsigned long long acc2 = 0ull;
#pragma unroll
            for (int j = 0; j < 16; j++)
                FMA2(acc2, GG2[j], PW[(2 * p + j) & 15], acc2);
            float lo, hi; UPK2(lo, hi, acc2);
            orow[2 * p]     = lo;
            orow[2 * p + 1] = hi;
            if (p < 7) {
                const float s1 = hv(s0 + 2 * p + 17); PK2(PW[(2 * p + 16) & 15], prev, s1); prev = s1;
                const float s2 = hv(s0 + 2 * p + 18); PK2(PW[(2 * p + 17) & 15], prev, s2); prev = s2;
            }
        }
    }
    __syncthreads();

    // coalesced planar store
    {
        const int c = t >> 7, w = t & 127;
        const size_t gbase = ((size_t)(c * 2 + b) << 21) + ((size_t)d << 14) + w;
#pragma unroll
        for (int hl = 0; hl < 16; hl++)
            d_F3[gbase + ((size_t)(h0 + hl) << 7)] = OUT[(c * 16 + hl) * 129 + w];
    }
}

// ---------------- warp: image trilinear + label nearest (no smem, no syncs) ---------
__device__ __forceinline__ float4 lerp4(float4 p, float4 q, float t) {
    float4 r;
    r.x = fmaf(t, q.x - p.x, p.x);
    r.y = fmaf(t, q.y - p.y, p.y);
    r.z = fmaf(t, q.z - p.z, p.z);
    r.w = fmaf(t, q.w - p.w, p.w);
    return r;
}

// grid (32, 128, 2) = (h-quad, d, b); 512 threads = 4 h-pencils x 128 w
__global__ __launch_bounds__(512) void warp_kernel(
    const float* __restrict__ img, const int* __restrict__ lab, float* __restrict__ out)
{
    const int t = threadIdx.x;
    const int d = blockIdx.y, b = blockIdx.z;
    const int hl = t >> 7, w = t & 127;
    const int h = blockIdx.x * 4 + hl;

    // direct planar flow reads: consecutive lanes = consecutive w -> fully coalesced
    const size_t fb = ((size_t)b << 21) + ((size_t)d << 14) + (h << 7) + w;
    const float f0 = __ldg(&d_F3[fb]);                        // c=0
    const float f1 = __ldg(&d_F3[fb + (1u << 22)]);           // c=1
    const float f2 = __ldg(&d_F3[fb + (2u << 22)]);           // c=2

    const float wd = __fadd_rn((float)d, __fmul_rn(f0, 35.0f));
    const float wh = __fadd_rn((float)h, __fmul_rn(f1, 35.0f));
    const float ww = __fadd_rn((float)w, __fmul_rn(f2, 35.0f));

    const float fld = floorf(wd), flh = floorf(wh), flw = floorf(ww);
    const float td = wd - fld, th = wh - flh, tw = ww - flw;

    const int id = (int)fld, ih = (int)flh, iw = (int)flw;
    const int d0 = min(max(id,     0), 127), d1 = min(max(id + 1, 0), 127);
    const int h0 = min(max(ih,     0), 127), h1 = min(max(ih + 1, 0), 127);
    const int w0 = min(max(iw,     0), 127), w1 = min(max(iw + 1, 0), 127);

    const float4* __restrict__ I = reinterpret_cast<const float4*>(img);
    const int bbase = b << 21;

    const int r00 = bbase + (d0 * 128 + h0) * 128;
    const int r01 = bbase + (d0 * 128 + h1) * 128;
    const int r10 = bbase + (d1 * 128 + h0) * 128;
    const int r11 = bbase + (d1 * 128 + h1) * 128;

    const float4 a000 = I[r00 + w0], a001 = I[r00 + w1];
    const float4 a010 = I[r01 + w0], a011 = I[r01 + w1];
    const float4 a100 = I[r10 + w0], a101 = I[r10 + w1];
    const float4 a110 = I[r11 + w0], a111 = I[r11 + w1];

    const float4 c00 = lerp4(a000, a001, tw);
    const float4 c01 = lerp4(a010, a011, tw);
    const float4 c10 = lerp4(a100, a101, tw);
    const float4 c11 = lerp4(a110, a111, tw);
    const float4 c0  = lerp4(c00, c01, th);
    const float4 c1  = lerp4(c10, c11, th);

    const int oidx = bbase + (d * 128 + h) * 128 + w;
    __stcs(&reinterpret_cast<float4*>(out)[oidx], lerp4(c0, c1, td));

    const int nd = min(max((int)rintf(wd), 0), 127);
    const int nh = min(max((int)rintf(wh), 0), 127);
    const int nw = min(max((int)rintf(ww), 0), 127);
    __stcs(&out[IMG_ELEMS + oidx], (float)__ldg(&lab[bbase + (nd * 128 + nh) * 128 + nw]));
}

extern "C" void kernel_launch(void* const* d_in, const int* in_sizes, int n_in,
                              void* d_out, int out_size) {
    const float* img    = (const float*)d_in[0];
    const int*   lab    = (const int*)  d_in[1];
    const float* coarse = (const float*)d_in[2];
    float* out = (float*)d_out;

    const int hw_smem = (6192 + 6192) * (int)sizeof(float); // 49536 B
    static int attr_done = 0;
    if (!attr_done) {
        cudaFuncSetAttribute(flowHW_kernel, cudaFuncAttributeMaxDynamicSharedMemorySize, hw_smem);
        attr_done = 1;
    }

    flowD_kernel<<<dim3(4, 128, 2), 384>>>(coarse);
    flowHW_kernel<<<dim3(8, 128, 2), 384, hw_smem>>>();
    warp_kernel<<<dim3(32, 128, 2), 512>>>(img, lab, out);
}

// round 15
// speedup vs baseline: 1.1544x; 1.1544x over previous
#include <cuda_runtime.h>
#include <math.h>

// B=2, D=H=W=128, C=4 image; label int32 C=1; coarse flow [2,4,4,4,3].
// Output: image [2,128,128,128,4] f32 then label [2,128,128,128] (as float).
// Intermediate flow PLANAR: [c][b][d][h][w]

#define NVOX      (2*128*128*128)
#define IMG_ELEMS (NVOX*4)
#define FLOW_N    (NVOX*3)

__device__ float d_F2[FLOW_N];  // after resize + convD, planar
__device__ float d_F3[FLOW_N];  // after convH + convW,   planar

// ---- weight generation (exact op structure jax/numpy use) ----
__device__ __forceinline__ float keys_f32(float x) {
    if (x < 1.0f) {
        float t = __fadd_rn(__fmul_rn(1.5f, x), -2.5f);
        t = __fmul_rn(t, x); t = __fmul_rn(t, x);
        return __fadd_rn(t, 1.0f);
    }
    if (x < 2.0f) {
        float t = __fadd_rn(__fmul_rn(-0.5f, x), 2.5f);
        t = __fadd_rn(__fmul_rn(t, x), -4.0f);
        t = __fmul_rn(t, x);
        return __fadd_rn(t, 2.0f);
    }
    return 0.0f;
}

__device__ __forceinline__ void gen_W_row(float* Wrow, int x) {
    float s = __fadd_rn(__fdiv_rn(__fadd_rn((float)x, 0.5f), 32.0f), -0.5f);
    float wv[4];
#pragma unroll
    for (int a = 0; a < 4; a++) wv[a] = keys_f32(fabsf(__fadd_rn(s, -(float)a)));
    float tot = __fadd_rn(__fadd_rn(__fadd_rn(wv[0], wv[1]), wv[2]), wv[3]);
#pragma unroll
    for (int a = 0; a < 4; a++) Wrow[a] = __fdiv_rn(wv[a], tot);
}

// ---------------- fused resizeD+resizeH+resizeW+convD (planar out) ----------------
// A2h stored transposed [ld][c][e] so b1() is one broadcast LDS.128.
__global__ __launch_bounds__(384, 4) void flowD_kernel(const float* __restrict__ coarse) {
    __shared__ float  cf[192];
    __shared__ float4 A2h4[48 * 3];     // [ld][c] -> (e0,e1,e2,e3)
    __shared__ float  Ws[128][4];
    __shared__ float  Gs[16];
    __shared__ double gtmp[16];
    const int t = threadIdx.x;
    const int t0 = blockIdx.x * 32;
    const int h = blockIdx.y, b = blockIdx.z;
    const int dplo = t0 - 7;

    if (t < 128) gen_W_row(Ws[t], t);
    if (t >= 128 && t < 144) { double o = (double)(t - 128 - 7); gtmp[t - 128] = exp(-o * o / 12.5); }
    if (t >= 192 && t < 384) cf[t - 192] = coarse[b * 192 + (t - 192)];
    __syncthreads();
    if (t < 16) {
        double gs = 0.0;
        for (int j = 0; j < 16; j++) gs += gtmp[j];
        Gs[t] = (float)(gtmp[t] / gs);
    }
    __syncthreads();

    float* A2h = reinterpret_cast<float*>(A2h4);
    const float wh0 = Ws[h][0], wh1 = Ws[h][1], wh2 = Ws[h][2], wh3 = Ws[h][3];
    for (int i = t; i < 48 * 12; i += 384) {
        const int ld = i / 12, r = i - ld * 12;
        const int c = r >> 2, e = r & 3;          // transposed slot
        const int dp = dplo + ld;
        float acc = 0.0f;
        if (dp >= 0 && dp < 128) {
#pragma unroll
            for (int bb = 0; bb < 4; bb++) {
                float a1 = 0.0f;
#pragma unroll
                for (int a = 0; a < 4; a++)
                    a1 = fmaf(Ws[dp][a], cf[a * 48 + bb * 12 + e * 3 + c], a1);
                const float whb = (bb == 0) ? wh0 : (bb == 1) ? wh1 : (bb == 2) ? wh2 : wh3;
                acc = fmaf(whb, a1, acc);
            }
        }
        A2h[i] = acc;
    }
    __syncthreads();

    const int c = t >> 7, w = t & 127;
    const float ww0 = Ws[w][0], ww1 = Ws[w][1], ww2 = Ws[w][2], ww3 = Ws[w][3];

    auto b1 = [&](int ld) -> float {
        const int dp = dplo + ld;
        if (dp < 0 || dp >= 128) return 0.0f;
        const float4 v = A2h4[ld * 3 + c];        // broadcast LDS.128
        float acc = 0.0f;
        acc = fmaf(ww0, v.x, acc);
        acc = fmaf(ww1, v.y, acc);
        acc = fmaf(ww2, v.z, acc);
        acc = fmaf(ww3, v.w, acc);
        return acc;
    };

    float g[16];
#pragma unroll
    for (int j = 0; j < 16; j++) g[j] = Gs[j];

    float win[16];
#pragma unroll
    for (int j = 0; j < 16; j++) win[j] = b1(j);

    size_t obase = ((size_t)(c * 2 + b) << 21) + ((size_t)t0 << 14) + (h << 7) + w;
#pragma unroll
    for (int dl = 0; dl < 32; dl++) {
        float acc = 0.0f;
#pragma unroll
        for (int j = 0; j < 16; j++)
            acc = fmaf(g[j], win[(dl + j) & 15], acc);   // j ascending: bit-exact
        d_F2[obase] = acc;
        obase += 16384;
        if (dl < 31) win[dl & 15] = b1(dl + 16);
    }
}

// ---------------- fused convH + convW (convH reads GLOBAL directly; low smem) --------
// grid (8, 128, 2) = (h-tile of 16, d, b); 384 threads
// dyn smem: H [48][129]; OUT [48][129].  total 49536 B
extern __shared__ float dyn_smem[];
__global__ __launch_bounds__(384) void flowHW_kernel() {
    float* H   = dyn_smem;
    float* OUT = dyn_smem + 6192;
    __shared__ float  Gs[16];
    __shared__ double gtmp[16];
    const int t = threadIdx.x;
    const int h0 = blockIdx.x * 16;
    const int d = blockIdx.y, b = blockIdx.z;

    if (t < 16) { double o = (double)(t - 7); gtmp[t] = exp(-o * o / 12.5); }
    __syncthreads();
    if (t < 16) {
        double gs = 0.0;
        for (int j = 0; j < 16; j++) gs += gtmp[j];
        Gs[t] = (float)(gtmp[t] / gs);
    }
    __syncthreads();

    float g[16];
#pragma unroll
    for (int j = 0; j < 16; j++) g[j] = Gs[j];

    // convH, sliding along h, window filled straight from global F2
    {
        const int c = t >> 7, w = t & 127;
        const float* gcol = d_F2 + ((size_t)(c * 2 + b) << 21) + ((size_t)d << 14) + w;
        float win[16];
#pragma unroll
        for (int j = 0; j < 16; j++) {
            const int hp = h0 - 7 + j;
            win[j] = (hp >= 0 && hp < 128) ? gcol[(size_t)hp << 7] : 0.0f;
        }
#pragma unroll
        for (int hl = 0; hl < 16; hl++) {
            float acc = 0.0f;
#pragma unroll
            for (int j = 0; j < 16; j++)
                acc = fmaf(g[j], win[(hl + j) & 15], acc);
            H[(c * 16 + hl) * 129 + w] = acc;
            if (hl < 15) {
                const int hp = h0 + 9 + hl;
                win[hl & 15] = (hp < 128) ? gcol[(size_t)hp << 7] : 0.0f;
            }
        }
    }
    __syncthreads();

    // convW, sliding along w. chunk-major: t = q*48 + pi (pi = c*16+hl)
    {
        const int q = t / 48, pi = t - q * 48;
        const int s0 = q * 16 - 7;
        const float* row = H + pi * 129;
        auto hv = [&](int s) -> float { return (s >= 0 && s < 128) ? row[s] : 0.0f; };
        float win[16];
#pragma unroll
        for (int j = 0; j < 16; j++) win[j] = hv(s0 + j);
        float* orow = OUT + pi * 129 + q * 16;
#pragma unroll
        for (int wl = 0; wl < 16; wl++) {
            float acc = 0.0f;
#pragma unroll
            for (int j = 0; j < 16; j++)
                acc = fmaf(g[j], win[(wl + j) & 15], acc);
            orow[wl] = acc;
            if (wl < 15) win[wl & 15] = hv(s0 + wl + 16);
        }
    }
    __syncthreads();

    // coalesced planar store
    {
        const int c = t >> 7, w = t & 127;
        const size_t gbase = ((size_t)(c * 2 + b) << 21) + ((size_t)d << 14) + w;
#pragma unroll
        for (int hl = 0; hl < 16; hl++)
            d_F3[gbase + ((size_t)(h0 + hl) << 7)] = OUT[(c * 16 + hl) * 129 + w];
    }
}

// ---------------- warp: image trilinear + label nearest (no smem, no syncs) ---------
__device__ __forceinline__ float4 lerp4(float4 p, float4 q, float t) {
    float4 r;
    r.x = fmaf(t, q.x - p.x, p.x);
    r.y = fmaf(t, q.y - p.y, p.y);
    r.z = fmaf(t, q.z - p.z, p.z);
    r.w = fmaf(t, q.w - p.w, p.w);
    return r;
}

// grid (32, 128, 2) = (h-quad, d, b); 512 threads = 4 h-pencils x 128 w
__global__ __launch_bounds__(512) void warp_kernel(
    const float* __restrict__ img, const int* __restrict__ lab, float* __restrict__ out)
{
    const int t = threadIdx.x;
    const int d = blockIdx.y, b = blockIdx.z;
    const int hl = t >> 7, w = t & 127;
    const int h = blockIdx.x * 4 + hl;

    // direct planar flow reads: consecutive lanes = consecutive w -> fully coalesced
    const size_t fb = ((size_t)b << 21) + ((size_t)d << 14) + (h << 7) + w;
    const float f0 = __ldg(&d_F3[fb]);                        // c=0
    const float f1 = __ldg(&d_F3[fb + (1u << 22)]);           // c=1
    const float f2 = __ldg(&d_F3[fb + (2u << 22)]);           // c=2

    const float wd = __fadd_rn((float)d, __fmul_rn(f0, 35.0f));
    const float wh = __fadd_rn((float)h, __fmul_rn(f1, 35.0f));
    const float ww = __fadd_rn((float)w, __fmul_rn(f2, 35.0f));

    const float fld = floorf(wd), flh = floorf(wh), flw = floorf(ww);
    const float td = wd - fld, th = wh - flh, tw = ww - flw;

    const int id = (int)fld, ih = (int)flh, iw = (int)flw;
    const int d0 = min(max(id,     0), 127), d1 = min(max(id + 1, 0), 127);
    const int h0 = min(max(ih,     0), 127), h1 = min(max(ih + 1, 0), 127);
    const int w0 = min(max(iw,     0), 127), w1 = min(max(iw + 1, 0), 127);

    const float4* __restrict__ I = reinterpret_cast<const float4*>(img);
    const int bbase = b << 21;

    const int r00 = bbase + (d0 * 128 + h0) * 128;
    const int r01 = bbase + (d0 * 128 + h1) * 128;
    const int r10 = bbase + (d1 * 128 + h0) * 128;
    const int r11 = bbase + (d1 * 128 + h1) * 128;

    const float4 a000 = I[r00 + w0], a001 = I[r00 + w1];
    const float4 a010 = I[r01 + w0], a011 = I[r01 + w1];
    const float4 a100 = I[r10 + w0], a101 = I[r10 + w1];
    const float4 a110 = I[r11 + w0], a111 = I[r11 + w1];

    const float4 c00 = lerp4(a000, a001, tw);
    const float4 c01 = lerp4(a010, a011, tw);
    const float4 c10 = lerp4(a100, a101, tw);
    const float4 c11 = lerp4(a110, a111, tw);
    const float4 c0  = lerp4(c00, c01, th);
    const float4 c1  = lerp4(c10, c11, th);

    const int oidx = bbase + (d * 128 + h) * 128 + w;
    __stcs(&reinterpret_cast<float4*>(out)[oidx], lerp4(c0, c1, td));

    const int nd = min(max((int)rintf(wd), 0), 127);
    const int nh = min(max((int)rintf(wh), 0), 127);
    const int nw = min(max((int)rintf(ww), 0), 127);
    __stcs(&out[IMG_ELEMS + oidx], (float)__ldg(&lab[bbase + (nd * 128 + nh) * 128 + nw]));
}

extern "C" void kernel_launch(void* const* d_in, const int* in_sizes, int n_in,
                              void* d_out, int out_size) {
    const float* img    = (const float*)d_in[0];
    const int*   lab    = (const int*)  d_in[1];
    const float* coarse = (const float*)d_in[2];
    float* out = (float*)d_out;

    const int hw_smem = (6192 + 6192) * (int)sizeof(float); // 49536 B
    static int attr_done = 0;
    if (!attr_done) {
        cudaFuncSetAttribute(flowHW_kernel, cudaFuncAttributeMaxDynamicSharedMemorySize, hw_smem);
        attr_done = 1;
    }

    flowD_kernel<<<dim3(4, 128, 2), 384>>>(coarse);
    flowHW_kernel<<<dim3(8, 128, 2), 384, hw_smem>>>();
    warp_kernel<<<dim3(32, 128, 2), 512>>>(img, lab, out);
}